// round 1
// baseline (speedup 1.0000x reference)
#include <cuda_runtime.h>
#include <math.h>

// Problem constants (fixed by the reference)
#define Bq   2
#define Sq   2048
#define HIDq 4096
#define NHq  32
#define NKVq 8
#define HDq  128
#define WINq 1024

// Scratch (no cudaMalloc allowed): ~167 MB of __device__ globals
__device__ float g_q  [(size_t)Bq * Sq * NHq  * HDq];
__device__ float g_k  [(size_t)Bq * Sq * NKVq * HDq];
__device__ float g_v  [(size_t)Bq * Sq * NKVq * HDq];
__device__ float g_att[(size_t)Bq * Sq * NHq  * HDq];

// ---------------------------------------------------------------------------
// SGEMM: C[M,N] = A[M,K] @ B[K,N], all row-major, fp32.
// 128x128 block tile, K-tile 16, 256 threads, 8x8 micro-tile per thread.
// Requires M % 128 == 0, N % 128 == 0, K % 16 == 0 (true for all our shapes).
// ---------------------------------------------------------------------------
__global__ __launch_bounds__(256, 2)
void sgemm128(const float* __restrict__ A, const float* __restrict__ Bm,
              float* __restrict__ C, int N, int K)
{
    __shared__ float As[16][128];   // transposed A tile: As[k][m]
    __shared__ float Bs[16][128];   // Bs[k][n]

    const int tid = threadIdx.x;
    const int tx = tid & 15, ty = tid >> 4;
    const int m0 = blockIdx.y << 7;
    const int n0 = blockIdx.x << 7;

    float acc[8][8];
#pragma unroll
    for (int i = 0; i < 8; i++)
#pragma unroll
        for (int j = 0; j < 8; j++) acc[i][j] = 0.f;

    for (int k0 = 0; k0 < K; k0 += 16) {
        // A tile: 128 rows x 16 cols -> 512 float4, 2 per thread
#pragma unroll
        for (int t = 0; t < 2; t++) {
            int v = tid + (t << 8);
            int r = v >> 2, c4 = (v & 3) << 2;
            const float4 f = *(const float4*)(A + (size_t)(m0 + r) * K + k0 + c4);
            As[c4 + 0][r] = f.x; As[c4 + 1][r] = f.y;
            As[c4 + 2][r] = f.z; As[c4 + 3][r] = f.w;
        }
        // B tile: 16 rows x 128 cols -> 512 float4, 2 per thread
#pragma unroll
        for (int t = 0; t < 2; t++) {
            int v = tid + (t << 8);
            int r = v >> 5, c4 = (v & 31) << 2;
            *(float4*)&Bs[r][c4] = *(const float4*)(Bm + (size_t)(k0 + r) * N + n0 + c4);
        }
        __syncthreads();
#pragma unroll
        for (int kk = 0; kk < 16; kk++) {
            float a[8], b[8];
            *(float4*)(a)     = *(const float4*)&As[kk][ty * 8];
            *(float4*)(a + 4) = *(const float4*)&As[kk][ty * 8 + 4];
            *(float4*)(b)     = *(const float4*)&Bs[kk][tx * 8];
            *(float4*)(b + 4) = *(const float4*)&Bs[kk][tx * 8 + 4];
#pragma unroll
            for (int i = 0; i < 8; i++)
#pragma unroll
                for (int j = 0; j < 8; j++)
                    acc[i][j] += a[i] * b[j];
        }
        __syncthreads();
    }

#pragma unroll
    for (int i = 0; i < 8; i++) {
        float* Cp = C + (size_t)(m0 + ty * 8 + i) * N + n0 + tx * 8;
        *(float4*)(Cp)     = make_float4(acc[i][0], acc[i][1], acc[i][2], acc[i][3]);
        *(float4*)(Cp + 4) = make_float4(acc[i][4], acc[i][5], acc[i][6], acc[i][7]);
    }
}

// ---------------------------------------------------------------------------
// RoPE (in place). x: [B, S, nheads, 128]. Pair (d, d+64), d in [0,64).
// inv_freq[d] = 10000^(-2d/128) = 2^(-(log2(1e4)/64) * d)
// out[d]    = x[d]*cos - x[d+64]*sin ; out[d+64] = x[d+64]*cos + x[d]*sin
// ---------------------------------------------------------------------------
__global__ void rope_kernel(float* __restrict__ x, const int* __restrict__ pos,
                            int nheads, int total)
{
    int idx = blockIdx.x * blockDim.x + threadIdx.x;
    if (idx >= total) return;
    int d  = idx & 63;
    int h  = (idx >> 6) % nheads;
    int bs = idx / (nheads << 6);

    float p   = (float)pos[bs];
    float inv = exp2f(-0.20762050593046014f * (float)d);  // log2(10000)/64
    float ang = p * inv;
    float s, c;
    sincosf(ang, &s, &c);

    float* base = x + ((size_t)bs * nheads + h) * HDq;
    float x1 = base[d], x2 = base[d + 64];
    base[d]      = x1 * c - x2 * s;
    base[d + 64] = x2 * c + x1 * s;
}

// ---------------------------------------------------------------------------
// Flash attention with sliding-window causal mask + GQA (n_rep = 4).
// Grid: (B*NH, S/64). Block: 256 threads.
// Per block: 64 Q rows of one head. Iterates K tiles of 64 inside the band
// [qi0-1024, qi0] only (<= 17 tiles).
// Thread grid 16x16: thread (ty,tx) owns Q rows ty*4..+3.
//   QK^T: 4x4 scores per thread (cols tx*4..+3)
//   PV  : 4 rows x 8 out cols (cols tx*8..+7)
// K smem tile is XOR-swizzled ([64][128], chunk c4 stored at c4 ^ (row>>2))
// for conflict-free LDS.128 in both store and load phases.
// ---------------------------------------------------------------------------
__global__ __launch_bounds__(256, 2)
void attn_kernel(const float* __restrict__ q, const float* __restrict__ kg,
                 const float* __restrict__ vg, const int* __restrict__ am,
                 float* __restrict__ outp)
{
    extern __shared__ float sm[];
    float* Qs = sm;              // [64][132] natural, padded
    float* KV = sm + 8448;       // K swizzled [64][128], then V natural [64][132]
    float* Ps = sm + 16896;      // [64][68]
    int*   mk = (int*)(sm + 21248);  // [64]

    const int tid = threadIdx.x;
    const int tx = tid & 15, ty = tid >> 4;
    const int b = blockIdx.x >> 5, h = blockIdx.x & 31;
    const int kvh = h >> 2;                     // repeat_interleave: h // n_rep
    const int qi0 = blockIdx.y << 6;

    // Load Q tile (rows qi0..qi0+63 of head h), row stride NH*HD in gmem
    {
        const float* qb = q + ((size_t)(b * Sq + qi0) * NHq + h) * HDq;
#pragma unroll
        for (int t = 0; t < 8; t++) {
            int i = tid + (t << 8);
            int r = i >> 5, c4 = (i & 31) << 2;
            *(float4*)&Qs[r * 132 + c4] =
                *(const float4*)(qb + (size_t)r * (NHq * HDq) + c4);
        }
    }

    float m_r[4], l_r[4], accv[4][8];
#pragma unroll
    for (int i = 0; i < 4; i++) {
        m_r[i] = -1e30f; l_r[i] = 0.f;
#pragma unroll
        for (int j = 0; j < 8; j++) accv[i][j] = 0.f;
    }

    const float scale = 0.08838834764831845f;   // 1/sqrt(128)
    int klo = qi0 - WINq; if (klo < 0) klo = 0;

    for (int k0 = klo; k0 <= qi0; k0 += 64) {
        __syncthreads();   // previous tile's V reads finished
        // Load K tile, swizzled
        {
            const float* kb = kg + ((size_t)(b * Sq + k0) * NKVq + kvh) * HDq;
#pragma unroll
            for (int t = 0; t < 8; t++) {
                int i = tid + (t << 8);
                int r = i >> 5, c4 = i & 31;
                int sc = (c4 ^ (r >> 2)) & 31;
                *(float4*)&KV[r * 128 + sc * 4] =
                    *(const float4*)(kb + (size_t)r * (NKVq * HDq) + (c4 << 2));
            }
        }
        if (tid < 64) mk[tid] = am[b * Sq + k0 + tid];
        __syncthreads();

        // ---- S = Q @ K^T (4x4 per thread) ----
        float sreg[4][4];
#pragma unroll
        for (int i = 0; i < 4; i++)
#pragma unroll
            for (int j = 0; j < 4; j++) sreg[i][j] = 0.f;

#pragma unroll 4
        for (int kk4 = 0; kk4 < 32; kk4++) {
            float4 a4[4], b4[4];
#pragma unroll
            for (int i = 0; i < 4; i++)
                a4[i] = *(const float4*)&Qs[(ty * 4 + i) * 132 + (kk4 << 2)];
#pragma unroll
            for (int j = 0; j < 4; j++)
                b4[j] = *(const float4*)&KV[(tx * 4 + j) * 128 + (((kk4 ^ tx) & 31) << 2)];
#pragma unroll
            for (int i = 0; i < 4; i++)
#pragma unroll
                for (int j = 0; j < 4; j++) {
                    sreg[i][j] += a4[i].x * b4[j].x;
                    sreg[i][j] += a4[i].y * b4[j].y;
                    sreg[i][j] += a4[i].z * b4[j].z;
                    sreg[i][j] += a4[i].w * b4[j].w;
                }
        }

        // ---- mask + online softmax ----
        float newm[4], alpha[4], rs[4];
#pragma unroll
        for (int i = 0; i < 4; i++) {
            int qi = qi0 + ty * 4 + i;
            float mx = -1e30f;
#pragma unroll
            for (int j = 0; j < 4; j++) {
                int kj = k0 + tx * 4 + j;
                bool valid = (kj <= qi) && (kj >= qi - WINq) && (mk[tx * 4 + j] > 0);
                sreg[i][j] = valid ? sreg[i][j] * scale : -1e30f;
                mx = fmaxf(mx, sreg[i][j]);
            }
            // row reduce across 16 tx lanes (aligned 16-lane groups in warp)
            mx = fmaxf(mx, __shfl_xor_sync(0xffffffffu, mx, 1));
            mx = fmaxf(mx, __shfl_xor_sync(0xffffffffu, mx, 2));
            mx = fmaxf(mx, __shfl_xor_sync(0xffffffffu, mx, 4));
            mx = fmaxf(mx, __shfl_xor_sync(0xffffffffu, mx, 8));
            newm[i]  = fmaxf(m_r[i], mx);
            alpha[i] = expf(m_r[i] - newm[i]);
            float s = 0.f;
#pragma unroll
            for (int j = 0; j < 4; j++) {
                float p = expf(sreg[i][j] - newm[i]);
                sreg[i][j] = p;
                s += p;
            }
            s += __shfl_xor_sync(0xffffffffu, s, 1);
            s += __shfl_xor_sync(0xffffffffu, s, 2);
            s += __shfl_xor_sync(0xffffffffu, s, 4);
            s += __shfl_xor_sync(0xffffffffu, s, 8);
            rs[i] = s;
        }
#pragma unroll
        for (int i = 0; i < 4; i++) {
            l_r[i] = l_r[i] * alpha[i] + rs[i];
            m_r[i] = newm[i];
#pragma unroll
            for (int j = 0; j < 8; j++) accv[i][j] *= alpha[i];
            *(float4*)&Ps[(ty * 4 + i) * 68 + tx * 4] =
                make_float4(sreg[i][0], sreg[i][1], sreg[i][2], sreg[i][3]);
        }
        __syncthreads();   // K reads done, Ps written

        // Load V tile into the same buffer (natural layout, pad 132)
        {
            const float* vb = vg + ((size_t)(b * Sq + k0) * NKVq + kvh) * HDq;
#pragma unroll
            for (int t = 0; t < 8; t++) {
                int i = tid + (t << 8);
                int r = i >> 5, c4 = (i & 31) << 2;
                *(float4*)&KV[r * 132 + c4] =
                    *(const float4*)(vb + (size_t)r * (NKVq * HDq) + c4);
            }
        }
        __syncthreads();

        // ---- acc += P @ V (4 rows x 8 cols per thread) ----
#pragma unroll 4
        for (int kk4 = 0; kk4 < 16; kk4++) {
            float4 p4[4];
#pragma unroll
            for (int i = 0; i < 4; i++)
                p4[i] = *(const float4*)&Ps[(ty * 4 + i) * 68 + (kk4 << 2)];
#pragma unroll
            for (int u = 0; u < 4; u++) {
                int kk = (kk4 << 2) + u;
                float4 v0 = *(const float4*)&KV[kk * 132 + tx * 8];
                float4 v1 = *(const float4*)&KV[kk * 132 + tx * 8 + 4];
#pragma unroll
                for (int i = 0; i < 4; i++) {
                    float pv = (u == 0) ? p4[i].x : (u == 1) ? p4[i].y
                             : (u == 2) ? p4[i].z : p4[i].w;
                    accv[i][0] += pv * v0.x; accv[i][1] += pv * v0.y;
                    accv[i][2] += pv * v0.z; accv[i][3] += pv * v0.w;
                    accv[i][4] += pv * v1.x; accv[i][5] += pv * v1.y;
                    accv[i][6] += pv * v1.z; accv[i][7] += pv * v1.w;
                }
            }
        }
    }

    // Epilogue: out = acc / l
#pragma unroll
    for (int i = 0; i < 4; i++) {
        float invl = 1.0f / l_r[i];
        int row = qi0 + ty * 4 + i;
        float* ob = outp + ((size_t)(b * Sq + row) * NHq + h) * HDq + tx * 8;
        *(float4*)(ob)     = make_float4(accv[i][0] * invl, accv[i][1] * invl,
                                         accv[i][2] * invl, accv[i][3] * invl);
        *(float4*)(ob + 4) = make_float4(accv[i][4] * invl, accv[i][5] * invl,
                                         accv[i][6] * invl, accv[i][7] * invl);
    }
}

// ---------------------------------------------------------------------------
// Launch: QKV GEMMs -> RoPE(q,k) -> attention -> O GEMM (into d_out).
// Graph-capturable: kernel launches only, no sync/alloc.
// ---------------------------------------------------------------------------
extern "C" void kernel_launch(void* const* d_in, const int* in_sizes, int n_in,
                              void* d_out, int out_size)
{
    const float* hs    = (const float*)d_in[0];
    const int*   amask = (const int*)  d_in[1];
    const int*   pos   = (const int*)  d_in[2];
    const float* qw    = (const float*)d_in[3];
    const float* kw    = (const float*)d_in[4];
    const float* vw    = (const float*)d_in[5];
    const float* ow    = (const float*)d_in[6];
    float*       out   = (float*)d_out;

    float *gq, *gk, *gv, *ga;
    cudaGetSymbolAddress((void**)&gq, g_q);
    cudaGetSymbolAddress((void**)&gk, g_k);
    cudaGetSymbolAddress((void**)&gv, g_v);
    cudaGetSymbolAddress((void**)&ga, g_att);

    const int attn_smem = 21248 * 4 + 64 * 4;   // 85,248 B
    cudaFuncSetAttribute(attn_kernel, cudaFuncAttributeMaxDynamicSharedMemorySize,
                         attn_smem);

    dim3 blk(256);

    // QKV projections: M = B*S = 4096 (grid.y = 32)
    sgemm128<<<dim3(32, 32), blk>>>(hs, qw, gq, NHq * HDq, HIDq);
    sgemm128<<<dim3(8, 32),  blk>>>(hs, kw, gk, NKVq * HDq, HIDq);
    sgemm128<<<dim3(8, 32),  blk>>>(hs, vw, gv, NKVq * HDq, HIDq);

    // RoPE in place
    {
        int tq = Bq * Sq * NHq * 64;
        int tk = Bq * Sq * NKVq * 64;
        rope_kernel<<<(tq + 255) / 256, 256>>>(gq, pos, NHq, tq);
        rope_kernel<<<(tk + 255) / 256, 256>>>(gk, pos, NKVq, tk);
    }

    // Attention
    attn_kernel<<<dim3(Bq * NHq, Sq / 64), blk, attn_smem>>>(gq, gk, gv, amask, ga);

    // Output projection into d_out
    sgemm128<<<dim3(32, 32), blk>>>(ga, ow, out, HIDq, NHq * HDq);
}

// round 4
// speedup vs baseline: 2.3021x; 2.3021x over previous
#include <cuda_runtime.h>
#include <cuda_bf16.h>
#include <cstdint>
#include <math.h>

// Problem constants
#define Bq   2
#define Sq   2048
#define HIDq 4096
#define NHq  32
#define NKVq 8
#define HDq  128
#define WINq 1024
#define Mtot (Bq * Sq)          // 4096 rows

// ---------------------------------------------------------------------------
// Scratch (__device__ globals; no cudaMalloc allowed)
// ---------------------------------------------------------------------------
__device__ float g_q  [(size_t)Mtot * NHq  * HDq];
__device__ float g_k  [(size_t)Mtot * NKVq * HDq];
__device__ float g_v  [(size_t)Mtot * NKVq * HDq];
__device__ float g_att[(size_t)Mtot * HIDq];

__device__ __nv_bfloat16 sA_hi [(size_t)Mtot * HIDq];
__device__ __nv_bfloat16 sA_lo [(size_t)Mtot * HIDq];
__device__ __nv_bfloat16 sWq_hi[(size_t)4096 * 4096];
__device__ __nv_bfloat16 sWq_lo[(size_t)4096 * 4096];
__device__ __nv_bfloat16 sWk_hi[(size_t)1024 * 4096];
__device__ __nv_bfloat16 sWk_lo[(size_t)1024 * 4096];
__device__ __nv_bfloat16 sWv_hi[(size_t)1024 * 4096];
__device__ __nv_bfloat16 sWv_lo[(size_t)1024 * 4096];
__device__ __nv_bfloat16 sWo_hi[(size_t)4096 * 4096];
__device__ __nv_bfloat16 sWo_lo[(size_t)4096 * 4096];
__device__ __nv_bfloat16 sAt_hi[(size_t)Mtot * HIDq];
__device__ __nv_bfloat16 sAt_lo[(size_t)Mtot * HIDq];

// ---------------------------------------------------------------------------
// Portable tensor-core primitives (valid under compute_103 virtual arch)
// ---------------------------------------------------------------------------
__device__ __forceinline__ void ldsm4(uint32_t* r, uint32_t addr) {
    asm volatile("ldmatrix.sync.aligned.m8n8.x4.shared.b16 {%0,%1,%2,%3}, [%4];"
        : "=r"(r[0]), "=r"(r[1]), "=r"(r[2]), "=r"(r[3]) : "r"(addr));
}

__device__ __forceinline__ void mma16816(float* d, const uint32_t* a, const uint32_t* b) {
    asm volatile("mma.sync.aligned.m16n8k16.row.col.f32.bf16.bf16.f32 "
        "{%0,%1,%2,%3}, {%4,%5,%6,%7}, {%8,%9}, {%0,%1,%2,%3};"
        : "+f"(d[0]), "+f"(d[1]), "+f"(d[2]), "+f"(d[3])
        : "r"(a[0]), "r"(a[1]), "r"(a[2]), "r"(a[3]), "r"(b[0]), "r"(b[1]));
}

__device__ __forceinline__ uint32_t smem_u32(const void* p) {
    uint32_t a;
    asm("{ .reg .u64 t; cvta.to.shared.u64 t, %1; cvt.u32.u64 %0, t; }"
        : "=r"(a) : "l"(p));
    return a;
}

#define CP_COMMIT() asm volatile("cp.async.commit_group;" ::: "memory")
#define CP_WAIT1()  asm volatile("cp.async.wait_group 1;" ::: "memory")
#define CP_WAIT0()  asm volatile("cp.async.wait_group 0;" ::: "memory")

// ---------------------------------------------------------------------------
// Conversion kernels
// ---------------------------------------------------------------------------
__global__ void split_kernel(const float4* __restrict__ x, uint2* __restrict__ h,
                             uint2* __restrict__ l, int n4)
{
    int i = blockIdx.x * blockDim.x + threadIdx.x;
    if (i >= n4) return;
    float4 v = x[i];
    __nv_bfloat16 h0 = __float2bfloat16(v.x), h1 = __float2bfloat16(v.y);
    __nv_bfloat16 h2 = __float2bfloat16(v.z), h3 = __float2bfloat16(v.w);
    __nv_bfloat16 l0 = __float2bfloat16(v.x - __bfloat162float(h0));
    __nv_bfloat16 l1 = __float2bfloat16(v.y - __bfloat162float(h1));
    __nv_bfloat16 l2 = __float2bfloat16(v.z - __bfloat162float(h2));
    __nv_bfloat16 l3 = __float2bfloat16(v.w - __bfloat162float(h3));
    uint2 ho, lo;
    ho.x = (uint32_t)__bfloat16_as_ushort(h0) | ((uint32_t)__bfloat16_as_ushort(h1) << 16);
    ho.y = (uint32_t)__bfloat16_as_ushort(h2) | ((uint32_t)__bfloat16_as_ushort(h3) << 16);
    lo.x = (uint32_t)__bfloat16_as_ushort(l0) | ((uint32_t)__bfloat16_as_ushort(l1) << 16);
    lo.y = (uint32_t)__bfloat16_as_ushort(l2) | ((uint32_t)__bfloat16_as_ushort(l3) << 16);
    h[i] = ho; l[i] = lo;
}

// W [K, N] row-major -> Th/Tl [N, K] K-major bf16 hi/lo
__global__ void transpose_split(const float* __restrict__ W,
                                __nv_bfloat16* __restrict__ Th,
                                __nv_bfloat16* __restrict__ Tl, int K, int N)
{
    __shared__ float t[32][33];
    int n0 = blockIdx.x << 5, k0 = blockIdx.y << 5;
    int tx = threadIdx.x, ty = threadIdx.y;
#pragma unroll
    for (int j = 0; j < 32; j += 8)
        t[ty + j][tx] = W[(size_t)(k0 + ty + j) * N + n0 + tx];
    __syncthreads();
#pragma unroll
    for (int j = 0; j < 32; j += 8) {
        float v = t[tx][ty + j];
        __nv_bfloat16 h = __float2bfloat16(v);
        float r = v - __bfloat162float(h);
        size_t o = (size_t)(n0 + ty + j) * K + k0 + tx;
        Th[o] = h; Tl[o] = __float2bfloat16(r);
    }
}

// ---------------------------------------------------------------------------
// HMMA bf16x3 GEMM: C[M,N] = A[M,K] @ B[N,K]^T  (A,B K-major, hi+lo split)
// 256 thr / 8 warps (2Mx4N), CTA 128x128, warp 64x32, K-chunk 64,
// cp.async double buffer (64KB/stage), swizzled 128B smem rows.
// ---------------------------------------------------------------------------
__device__ __forceinline__ void cp_tile(uint32_t sdst, const char* g, int K2,
                                        int kb, int tid)
{
#pragma unroll
    for (int t = 0; t < 4; t++) {
        int idx = tid + (t << 8);
        int r = idx >> 3, c = idx & 7;
        uint32_t phys = sdst + r * 128 + ((c ^ (r & 7)) << 4);
        uint64_t src = __cvta_generic_to_global(g + (size_t)r * K2 + kb + (c << 4));
        asm volatile("cp.async.cg.shared.global [%0], [%1], 16;"
                     :: "r"(phys), "l"(src));
    }
}

__global__ __launch_bounds__(256, 1)
void gemm_mma_bf16x3(const __nv_bfloat16* __restrict__ Ah,
                     const __nv_bfloat16* __restrict__ Al,
                     const __nv_bfloat16* __restrict__ Bh,
                     const __nv_bfloat16* __restrict__ Bl,
                     float* __restrict__ C, int N, int K)
{
    extern __shared__ __align__(128) char smc[];
    const uint32_t smb = smem_u32(smc);
    const int tid = threadIdx.x;
    const int lane = tid & 31, wid = tid >> 5;
    const int wm = (wid >> 2) << 6;    // warp M offset (0/64)
    const int wn = (wid & 3) << 5;     // warp N offset (0/32/64/96)
    const int n0 = blockIdx.x << 7, m0 = blockIdx.y << 7;
    const int K2 = K * 2;

    const char* gA0 = (const char*)(Ah + (size_t)m0 * K);
    const char* gA1 = (const char*)(Al + (size_t)m0 * K);
    const char* gB0 = (const char*)(Bh + (size_t)n0 * K);
    const char* gB1 = (const char*)(Bl + (size_t)n0 * K);

    // prologue: stage 0
    cp_tile(smb +     0, gA0, K2, 0, tid);
    cp_tile(smb + 16384, gA1, K2, 0, tid);
    cp_tile(smb + 32768, gB0, K2, 0, tid);
    cp_tile(smb + 49152, gB1, K2, 0, tid);
    CP_COMMIT();

    float acc[4][4][4];
#pragma unroll
    for (int i = 0; i < 4; i++)
#pragma unroll
        for (int j = 0; j < 4; j++)
#pragma unroll
            for (int q = 0; q < 4; q++) acc[i][j][q] = 0.f;

    // lane address components
    const int arow = (lane & 7) + ((lane >> 3) & 1) * 8;   // within m16
    const int abit = (lane >> 4) & 1;                      // A chunk bit
    const int brow = (lane & 7) + ((lane >> 4) & 1) * 8;   // within n16
    const int bbit = (lane >> 3) & 1;                      // B chunk bit

    const int NIT = K >> 6;
    for (int it = 0; it < NIT; it++) {
        const uint32_t cur = smb + (uint32_t)(it & 1) * 65536u;
        if (it + 1 < NIT) {
            const uint32_t nxt = smb + (uint32_t)((it + 1) & 1) * 65536u;
            const int kb = (it + 1) << 7;   // bytes: 64 elems * 2
            cp_tile(nxt +     0, gA0, K2, kb, tid);
            cp_tile(nxt + 16384, gA1, K2, kb, tid);
            cp_tile(nxt + 32768, gB0, K2, kb, tid);
            cp_tile(nxt + 49152, gB1, K2, kb, tid);
            CP_COMMIT();
            CP_WAIT1();
        } else {
            CP_WAIT0();
        }
        __syncthreads();

#pragma unroll
        for (int ks = 0; ks < 4; ks++) {
            uint32_t a_h[4][4], a_l[4][4], b_h[2][4], b_l[2][4];
#pragma unroll
            for (int i = 0; i < 4; i++) {
                int r = wm + (i << 4) + arow;
                uint32_t off = (uint32_t)r * 128 +
                               ((((ks << 1) + abit) ^ (r & 7)) << 4);
                ldsm4(a_h[i], cur + off);
                ldsm4(a_l[i], cur + 16384 + off);
            }
#pragma unroll
            for (int j = 0; j < 2; j++) {
                int r = wn + (j << 4) + brow;
                uint32_t off = (uint32_t)r * 128 +
                               ((((ks << 1) + bbit) ^ (r & 7)) << 4);
                ldsm4(b_h[j], cur + 32768 + off);
                ldsm4(b_l[j], cur + 49152 + off);
            }
#pragma unroll
            for (int i = 0; i < 4; i++)
#pragma unroll
                for (int jj = 0; jj < 4; jj++) {
                    const uint32_t* bh = &b_h[jj >> 1][(jj & 1) << 1];
                    const uint32_t* bl = &b_l[jj >> 1][(jj & 1) << 1];
                    mma16816(acc[i][jj], a_h[i], bh);   // hi*hi
                    mma16816(acc[i][jj], a_h[i], bl);   // hi*lo
                    mma16816(acc[i][jj], a_l[i], bh);   // lo*hi
                }
        }
        __syncthreads();
    }

    // epilogue
#pragma unroll
    for (int i = 0; i < 4; i++) {
        int row = m0 + wm + (i << 4) + (lane >> 2);
#pragma unroll
        for (int jj = 0; jj < 4; jj++) {
            int col = n0 + wn + (jj << 3) + ((lane & 3) << 1);
            float* p0 = C + (size_t)row * N + col;
            float* p1 = C + (size_t)(row + 8) * N + col;
            p0[0] = acc[i][jj][0]; p0[1] = acc[i][jj][1];
            p1[0] = acc[i][jj][2]; p1[1] = acc[i][jj][3];
        }
    }
}

// ---------------------------------------------------------------------------
// RoPE (unchanged)
// ---------------------------------------------------------------------------
__global__ void rope_kernel(float* __restrict__ x, const int* __restrict__ pos,
                            int nheads, int total)
{
    int idx = blockIdx.x * blockDim.x + threadIdx.x;
    if (idx >= total) return;
    int d  = idx & 63;
    int h  = (idx >> 6) % nheads;
    int bs = idx / (nheads << 6);

    float p   = (float)pos[bs];
    float inv = exp2f(-0.20762050593046014f * (float)d);
    float ang = p * inv;
    float s, c;
    sincosf(ang, &s, &c);

    float* base = x + ((size_t)bs * nheads + h) * HDq;
    float x1 = base[d], x2 = base[d + 64];
    base[d]      = x1 * c - x2 * s;
    base[d + 64] = x2 * c + x1 * s;
}

// ---------------------------------------------------------------------------
// Flash attention (unchanged from passing R1 kernel)
// ---------------------------------------------------------------------------
__global__ __launch_bounds__(256, 2)
void attn_kernel(const float* __restrict__ q, const float* __restrict__ kg,
                 const float* __restrict__ vg, const int* __restrict__ am,
                 float* __restrict__ outp)
{
    extern __shared__ __align__(1024) float smf[];
    float* Qs = smf;
    float* KV = smf + 8448;
    float* Ps = smf + 16896;
    int*   mk = (int*)(smf + 21248);

    const int tid = threadIdx.x;
    const int tx = tid & 15, ty = tid >> 4;
    const int b = blockIdx.x >> 5, h = blockIdx.x & 31;
    const int kvh = h >> 2;
    const int qi0 = blockIdx.y << 6;

    {
        const float* qb = q + ((size_t)(b * Sq + qi0) * NHq + h) * HDq;
#pragma unroll
        for (int t = 0; t < 8; t++) {
            int i = tid + (t << 8);
            int r = i >> 5, c4 = (i & 31) << 2;
            *(float4*)&Qs[r * 132 + c4] =
                *(const float4*)(qb + (size_t)r * (NHq * HDq) + c4);
        }
    }

    float m_r[4], l_r[4], accv[4][8];
#pragma unroll
    for (int i = 0; i < 4; i++) {
        m_r[i] = -1e30f; l_r[i] = 0.f;
#pragma unroll
        for (int j = 0; j < 8; j++) accv[i][j] = 0.f;
    }

    const float scale = 0.08838834764831845f;
    int klo = qi0 - WINq; if (klo < 0) klo = 0;

    for (int k0 = klo; k0 <= qi0; k0 += 64) {
        __syncthreads();
        {
            const float* kb = kg + ((size_t)(b * Sq + k0) * NKVq + kvh) * HDq;
#pragma unroll
            for (int t = 0; t < 8; t++) {
                int i = tid + (t << 8);
                int r = i >> 5, c4 = i & 31;
                int sc = (c4 ^ (r >> 2)) & 31;
                *(float4*)&KV[r * 128 + sc * 4] =
                    *(const float4*)(kb + (size_t)r * (NKVq * HDq) + (c4 << 2));
            }
        }
        if (tid < 64) mk[tid] = am[b * Sq + k0 + tid];
        __syncthreads();

        float sreg[4][4];
#pragma unroll
        for (int i = 0; i < 4; i++)
#pragma unroll
            for (int j = 0; j < 4; j++) sreg[i][j] = 0.f;

#pragma unroll 4
        for (int kk4 = 0; kk4 < 32; kk4++) {
            float4 a4[4], b4[4];
#pragma unroll
            for (int i = 0; i < 4; i++)
                a4[i] = *(const float4*)&Qs[(ty * 4 + i) * 132 + (kk4 << 2)];
#pragma unroll
            for (int j = 0; j < 4; j++)
                b4[j] = *(const float4*)&KV[(tx * 4 + j) * 128 + (((kk4 ^ tx) & 31) << 2)];
#pragma unroll
            for (int i = 0; i < 4; i++)
#pragma unroll
                for (int j = 0; j < 4; j++) {
                    sreg[i][j] += a4[i].x * b4[j].x;
                    sreg[i][j] += a4[i].y * b4[j].y;
                    sreg[i][j] += a4[i].z * b4[j].z;
                    sreg[i][j] += a4[i].w * b4[j].w;
                }
        }

        float newm[4], alpha[4], rs[4];
#pragma unroll
        for (int i = 0; i < 4; i++) {
            int qi = qi0 + ty * 4 + i;
            float mx = -1e30f;
#pragma unroll
            for (int j = 0; j < 4; j++) {
                int kj = k0 + tx * 4 + j;
                bool valid = (kj <= qi) && (kj >= qi - WINq) && (mk[tx * 4 + j] > 0);
                sreg[i][j] = valid ? sreg[i][j] * scale : -1e30f;
                mx = fmaxf(mx, sreg[i][j]);
            }
            mx = fmaxf(mx, __shfl_xor_sync(0xffffffffu, mx, 1));
            mx = fmaxf(mx, __shfl_xor_sync(0xffffffffu, mx, 2));
            mx = fmaxf(mx, __shfl_xor_sync(0xffffffffu, mx, 4));
            mx = fmaxf(mx, __shfl_xor_sync(0xffffffffu, mx, 8));
            newm[i]  = fmaxf(m_r[i], mx);
            alpha[i] = expf(m_r[i] - newm[i]);
            float s = 0.f;
#pragma unroll
            for (int j = 0; j < 4; j++) {
                float p = expf(sreg[i][j] - newm[i]);
                sreg[i][j] = p;
                s += p;
            }
            s += __shfl_xor_sync(0xffffffffu, s, 1);
            s += __shfl_xor_sync(0xffffffffu, s, 2);
            s += __shfl_xor_sync(0xffffffffu, s, 4);
            s += __shfl_xor_sync(0xffffffffu, s, 8);
            rs[i] = s;
        }
#pragma unroll
        for (int i = 0; i < 4; i++) {
            l_r[i] = l_r[i] * alpha[i] + rs[i];
            m_r[i] = newm[i];
#pragma unroll
            for (int j = 0; j < 8; j++) accv[i][j] *= alpha[i];
            *(float4*)&Ps[(ty * 4 + i) * 68 + tx * 4] =
                make_float4(sreg[i][0], sreg[i][1], sreg[i][2], sreg[i][3]);
        }
        __syncthreads();

        {
            const float* vb = vg + ((size_t)(b * Sq + k0) * NKVq + kvh) * HDq;
#pragma unroll
            for (int t = 0; t < 8; t++) {
                int i = tid + (t << 8);
                int r = i >> 5, c4 = (i & 31) << 2;
                *(float4*)&KV[r * 132 + c4] =
                    *(const float4*)(vb + (size_t)r * (NKVq * HDq) + c4);
            }
        }
        __syncthreads();

#pragma unroll 4
        for (int kk4 = 0; kk4 < 16; kk4++) {
            float4 p4[4];
#pragma unroll
            for (int i = 0; i < 4; i++)
                p4[i] = *(const float4*)&Ps[(ty * 4 + i) * 68 + (kk4 << 2)];
#pragma unroll
            for (int u = 0; u < 4; u++) {
                int kk = (kk4 << 2) + u;
                float4 v0 = *(const float4*)&KV[kk * 132 + tx * 8];
                float4 v1 = *(const float4*)&KV[kk * 132 + tx * 8 + 4];
#pragma unroll
                for (int i = 0; i < 4; i++) {
                    float pv = (u == 0) ? p4[i].x : (u == 1) ? p4[i].y
                             : (u == 2) ? p4[i].z : p4[i].w;
                    accv[i][0] += pv * v0.x; accv[i][1] += pv * v0.y;
                    accv[i][2] += pv * v0.z; accv[i][3] += pv * v0.w;
                    accv[i][4] += pv * v1.x; accv[i][5] += pv * v1.y;
                    accv[i][6] += pv * v1.z; accv[i][7] += pv * v1.w;
                }
            }
        }
    }

#pragma unroll
    for (int i = 0; i < 4; i++) {
        float invl = 1.0f / l_r[i];
        int row = qi0 + ty * 4 + i;
        float* ob = outp + ((size_t)(b * Sq + row) * NHq + h) * HDq + tx * 8;
        *(float4*)(ob)     = make_float4(accv[i][0] * invl, accv[i][1] * invl,
                                         accv[i][2] * invl, accv[i][3] * invl);
        *(float4*)(ob + 4) = make_float4(accv[i][4] * invl, accv[i][5] * invl,
                                         accv[i][6] * invl, accv[i][7] * invl);
    }
}

// ---------------------------------------------------------------------------
// Launch
// ---------------------------------------------------------------------------
extern "C" void kernel_launch(void* const* d_in, const int* in_sizes, int n_in,
                              void* d_out, int out_size)
{
    const float* hs    = (const float*)d_in[0];
    const int*   amask = (const int*)  d_in[1];
    const int*   pos   = (const int*)  d_in[2];
    const float* qw    = (const float*)d_in[3];
    const float* kw    = (const float*)d_in[4];
    const float* vw    = (const float*)d_in[5];
    const float* ow    = (const float*)d_in[6];
    float*       out   = (float*)d_out;

    float *gq, *gk, *gv, *ga;
    cudaGetSymbolAddress((void**)&gq, g_q);
    cudaGetSymbolAddress((void**)&gk, g_k);
    cudaGetSymbolAddress((void**)&gv, g_v);
    cudaGetSymbolAddress((void**)&ga, g_att);

    __nv_bfloat16 *ah, *al, *wqh, *wql, *wkh, *wkl, *wvh, *wvl, *woh, *wol, *ath, *atl;
    cudaGetSymbolAddress((void**)&ah,  sA_hi);  cudaGetSymbolAddress((void**)&al,  sA_lo);
    cudaGetSymbolAddress((void**)&wqh, sWq_hi); cudaGetSymbolAddress((void**)&wql, sWq_lo);
    cudaGetSymbolAddress((void**)&wkh, sWk_hi); cudaGetSymbolAddress((void**)&wkl, sWk_lo);
    cudaGetSymbolAddress((void**)&wvh, sWv_hi); cudaGetSymbolAddress((void**)&wvl, sWv_lo);
    cudaGetSymbolAddress((void**)&woh, sWo_hi); cudaGetSymbolAddress((void**)&wol, sWo_lo);
    cudaGetSymbolAddress((void**)&ath, sAt_hi); cudaGetSymbolAddress((void**)&atl, sAt_lo);

    const int gemm_smem = 131072;
    cudaFuncSetAttribute(gemm_mma_bf16x3, cudaFuncAttributeMaxDynamicSharedMemorySize,
                         gemm_smem);
    const int attn_smem = 21248 * 4 + 64 * 4;
    cudaFuncSetAttribute(attn_kernel, cudaFuncAttributeMaxDynamicSharedMemorySize,
                         attn_smem);

    // 1. split hidden_states -> bf16 hi/lo
    {
        int n4 = (Mtot * HIDq) / 4;
        split_kernel<<<(n4 + 255) / 256, 256>>>((const float4*)hs, (uint2*)ah, (uint2*)al, n4);
    }
    // 2. transpose + split weights to [N, K] bf16 hi/lo
    transpose_split<<<dim3(128, 128), dim3(32, 8)>>>(qw, wqh, wql, HIDq, 4096);
    transpose_split<<<dim3(32, 128),  dim3(32, 8)>>>(kw, wkh, wkl, HIDq, 1024);
    transpose_split<<<dim3(32, 128),  dim3(32, 8)>>>(vw, wvh, wvl, HIDq, 1024);
    transpose_split<<<dim3(128, 128), dim3(32, 8)>>>(ow, woh, wol, 4096, HIDq);

    // 3. QKV projections on tensor cores (HMMA)
    gemm_mma_bf16x3<<<dim3(32, 32), 256, gemm_smem>>>(ah, al, wqh, wql, gq, 4096, HIDq);
    gemm_mma_bf16x3<<<dim3(8, 32),  256, gemm_smem>>>(ah, al, wkh, wkl, gk, 1024, HIDq);
    gemm_mma_bf16x3<<<dim3(8, 32),  256, gemm_smem>>>(ah, al, wvh, wvl, gv, 1024, HIDq);

    // 4. RoPE in place
    {
        int tq = Mtot * NHq * 64;
        int tk = Mtot * NKVq * 64;
        rope_kernel<<<(tq + 255) / 256, 256>>>(gq, pos, NHq, tq);
        rope_kernel<<<(tk + 255) / 256, 256>>>(gk, pos, NKVq, tk);
    }

    // 5. attention
    attn_kernel<<<dim3(Bq * NHq, Sq / 64), 256, attn_smem>>>(gq, gk, gv, amask, ga);

    // 6. split attention output, O projection into d_out
    {
        int n4 = (Mtot * HIDq) / 4;
        split_kernel<<<(n4 + 255) / 256, 256>>>((const float4*)ga, (uint2*)ath, (uint2*)atl, n4);
    }
    gemm_mma_bf16x3<<<dim3(32, 32), 256, gemm_smem>>>(ath, atl, woh, wol, out, HIDq, 4096);
}

// round 8
// speedup vs baseline: 3.2158x; 1.3969x over previous
#include <cuda_runtime.h>
#include <cuda_bf16.h>
#include <cstdint>
#include <math.h>

// Problem constants
#define Bq   2
#define Sq   2048
#define HIDq 4096
#define NHq  32
#define NKVq 8
#define HDq  128
#define WINq 1024
#define Mtot (Bq * Sq)          // 4096 rows

// ---------------------------------------------------------------------------
// Scratch (__device__ globals; no cudaMalloc allowed)
// ---------------------------------------------------------------------------
__device__ float g_q  [(size_t)Mtot * NHq  * HDq];
__device__ float g_k  [(size_t)Mtot * NKVq * HDq];
__device__ float g_v  [(size_t)Mtot * NKVq * HDq];

__device__ __nv_bfloat16 sA_hi [(size_t)Mtot * HIDq];
__device__ __nv_bfloat16 sA_lo [(size_t)Mtot * HIDq];
__device__ __nv_bfloat16 sWq_hi[(size_t)4096 * 4096];
__device__ __nv_bfloat16 sWq_lo[(size_t)4096 * 4096];
__device__ __nv_bfloat16 sWk_hi[(size_t)1024 * 4096];
__device__ __nv_bfloat16 sWk_lo[(size_t)1024 * 4096];
__device__ __nv_bfloat16 sWv_hi[(size_t)1024 * 4096];
__device__ __nv_bfloat16 sWv_lo[(size_t)1024 * 4096];
__device__ __nv_bfloat16 sWo_hi[(size_t)4096 * 4096];
__device__ __nv_bfloat16 sWo_lo[(size_t)4096 * 4096];
__device__ __nv_bfloat16 sAt_hi[(size_t)Mtot * HIDq];
__device__ __nv_bfloat16 sAt_lo[(size_t)Mtot * HIDq];

// bf16 split Q/K/V for HMMA attention
__device__ __nv_bfloat16 sQh[(size_t)Mtot * NHq  * HDq];
__device__ __nv_bfloat16 sQl[(size_t)Mtot * NHq  * HDq];
__device__ __nv_bfloat16 sKh[(size_t)Mtot * NKVq * HDq];
__device__ __nv_bfloat16 sKl[(size_t)Mtot * NKVq * HDq];
__device__ __nv_bfloat16 sVh[(size_t)Mtot * NKVq * HDq];
__device__ __nv_bfloat16 sVl[(size_t)Mtot * NKVq * HDq];

// ---------------------------------------------------------------------------
// Portable tensor-core primitives (valid under compute_103 virtual arch)
// ---------------------------------------------------------------------------
__device__ __forceinline__ void ldsm4(uint32_t* r, uint32_t addr) {
    asm volatile("ldmatrix.sync.aligned.m8n8.x4.shared.b16 {%0,%1,%2,%3}, [%4];"
        : "=r"(r[0]), "=r"(r[1]), "=r"(r[2]), "=r"(r[3]) : "r"(addr));
}
__device__ __forceinline__ void ldsm4t(uint32_t* r, uint32_t addr) {
    asm volatile("ldmatrix.sync.aligned.m8n8.x4.trans.shared.b16 {%0,%1,%2,%3}, [%4];"
        : "=r"(r[0]), "=r"(r[1]), "=r"(r[2]), "=r"(r[3]) : "r"(addr));
}
__device__ __forceinline__ void mma16816(float* d, const uint32_t* a, const uint32_t* b) {
    asm volatile("mma.sync.aligned.m16n8k16.row.col.f32.bf16.bf16.f32 "
        "{%0,%1,%2,%3}, {%4,%5,%6,%7}, {%8,%9}, {%0,%1,%2,%3};"
        : "+f"(d[0]), "+f"(d[1]), "+f"(d[2]), "+f"(d[3])
        : "r"(a[0]), "r"(a[1]), "r"(a[2]), "r"(a[3]), "r"(b[0]), "r"(b[1]));
}
__device__ __forceinline__ uint32_t smem_u32(const void* p) {
    uint32_t a;
    asm("{ .reg .u64 t; cvta.to.shared.u64 t, %1; cvt.u32.u64 %0, t; }"
        : "=r"(a) : "l"(p));
    return a;
}
#define CP_COMMIT() asm volatile("cp.async.commit_group;" ::: "memory")
#define CP_WAIT1()  asm volatile("cp.async.wait_group 1;" ::: "memory")
#define CP_WAIT0()  asm volatile("cp.async.wait_group 0;" ::: "memory")

__device__ __forceinline__ void cp16(uint32_t sdst, const void* gsrc) {
    uint64_t s = __cvta_generic_to_global(gsrc);
    asm volatile("cp.async.cg.shared.global [%0], [%1], 16;" :: "r"(sdst), "l"(s));
}

// FMA-pipe exp (x <= 0): exp(x) = 2^(x*log2e), poly on [-0.5,0.5] + exponent splice
__device__ __forceinline__ float fexp(float x) {
    x = fmaxf(x, -80.0f);
    float t = x * 1.4426950408889634f;
    float fk = t + 12582912.0f;               // round-to-nearest int (magic)
    int   ki = __float_as_int(fk) - 0x4B400000;
    float r  = t - (fk - 12582912.0f);
    float p  = 0.0013333558f;
    p = fmaf(p, r, 0.0096181291f);
    p = fmaf(p, r, 0.0555041087f);
    p = fmaf(p, r, 0.2402265069f);
    p = fmaf(p, r, 0.6931471806f);
    p = fmaf(p, r, 1.0f);
    return __int_as_float(__float_as_int(p) + (ki << 23));
}

__device__ __forceinline__ uint32_t pack_bf2(float a, float b) {
    __nv_bfloat16 ha = __float2bfloat16(a), hb = __float2bfloat16(b);
    return (uint32_t)__bfloat16_as_ushort(ha) |
           ((uint32_t)__bfloat16_as_ushort(hb) << 16);
}

// ---------------------------------------------------------------------------
// Conversion kernels
// ---------------------------------------------------------------------------
__global__ void split_kernel(const float4* __restrict__ x, uint2* __restrict__ h,
                             uint2* __restrict__ l, int n4)
{
    int i = blockIdx.x * blockDim.x + threadIdx.x;
    if (i >= n4) return;
    float4 v = x[i];
    __nv_bfloat16 h0 = __float2bfloat16(v.x), h1 = __float2bfloat16(v.y);
    __nv_bfloat16 h2 = __float2bfloat16(v.z), h3 = __float2bfloat16(v.w);
    __nv_bfloat16 l0 = __float2bfloat16(v.x - __bfloat162float(h0));
    __nv_bfloat16 l1 = __float2bfloat16(v.y - __bfloat162float(h1));
    __nv_bfloat16 l2 = __float2bfloat16(v.z - __bfloat162float(h2));
    __nv_bfloat16 l3 = __float2bfloat16(v.w - __bfloat162float(h3));
    uint2 ho, lo;
    ho.x = (uint32_t)__bfloat16_as_ushort(h0) | ((uint32_t)__bfloat16_as_ushort(h1) << 16);
    ho.y = (uint32_t)__bfloat16_as_ushort(h2) | ((uint32_t)__bfloat16_as_ushort(h3) << 16);
    lo.x = (uint32_t)__bfloat16_as_ushort(l0) | ((uint32_t)__bfloat16_as_ushort(l1) << 16);
    lo.y = (uint32_t)__bfloat16_as_ushort(l2) | ((uint32_t)__bfloat16_as_ushort(l3) << 16);
    h[i] = ho; l[i] = lo;
}

// W [K, N] row-major -> Th/Tl [N, K] K-major bf16 hi/lo
__global__ void transpose_split(const float* __restrict__ W,
                                __nv_bfloat16* __restrict__ Th,
                                __nv_bfloat16* __restrict__ Tl, int K, int N)
{
    __shared__ float t[32][33];
    int n0 = blockIdx.x << 5, k0 = blockIdx.y << 5;
    int tx = threadIdx.x, ty = threadIdx.y;
#pragma unroll
    for (int j = 0; j < 32; j += 8)
        t[ty + j][tx] = W[(size_t)(k0 + ty + j) * N + n0 + tx];
    __syncthreads();
#pragma unroll
    for (int j = 0; j < 32; j += 8) {
        float v = t[tx][ty + j];
        __nv_bfloat16 h = __float2bfloat16(v);
        float r = v - __bfloat162float(h);
        size_t o = (size_t)(n0 + ty + j) * K + k0 + tx;
        Th[o] = h; Tl[o] = __float2bfloat16(r);
    }
}

// RoPE from fp32 input, writing split bf16 hi/lo
__global__ void rope_split(const float* __restrict__ x, const int* __restrict__ pos,
                           __nv_bfloat16* __restrict__ oh, __nv_bfloat16* __restrict__ ol,
                           int nheads, int total)
{
    int idx = blockIdx.x * blockDim.x + threadIdx.x;
    if (idx >= total) return;
    int d  = idx & 63;
    int h  = (idx >> 6) % nheads;
    int bs = idx / (nheads << 6);

    float p   = (float)pos[bs];
    float inv = exp2f(-0.20762050593046014f * (float)d);
    float ang = p * inv;
    float s, c;
    sincosf(ang, &s, &c);

    size_t base = ((size_t)bs * nheads + h) * HDq;
    float x1 = x[base + d], x2 = x[base + d + 64];
    float o1 = x1 * c - x2 * s;
    float o2 = x2 * c + x1 * s;
    __nv_bfloat16 h1 = __float2bfloat16(o1), h2 = __float2bfloat16(o2);
    oh[base + d]      = h1;
    oh[base + d + 64] = h2;
    ol[base + d]      = __float2bfloat16(o1 - __bfloat162float(h1));
    ol[base + d + 64] = __float2bfloat16(o2 - __bfloat162float(h2));
}

// ---------------------------------------------------------------------------
// HMMA bf16x3 GEMM (unchanged, proven in R4)
// ---------------------------------------------------------------------------
__device__ __forceinline__ void cp_tile(uint32_t sdst, const char* g, int K2,
                                        int kb, int tid)
{
#pragma unroll
    for (int t = 0; t < 4; t++) {
        int idx = tid + (t << 8);
        int r = idx >> 3, c = idx & 7;
        uint32_t phys = sdst + r * 128 + ((c ^ (r & 7)) << 4);
        cp16(phys, g + (size_t)r * K2 + kb + (c << 4));
    }
}

__global__ __launch_bounds__(256, 1)
void gemm_mma_bf16x3(const __nv_bfloat16* __restrict__ Ah,
                     const __nv_bfloat16* __restrict__ Al,
                     const __nv_bfloat16* __restrict__ Bh,
                     const __nv_bfloat16* __restrict__ Bl,
                     float* __restrict__ C, int N, int K)
{
    extern __shared__ __align__(128) char smc[];
    const uint32_t smb = smem_u32(smc);
    const int tid = threadIdx.x;
    const int lane = tid & 31, wid = tid >> 5;
    const int wm = (wid >> 2) << 6;
    const int wn = (wid & 3) << 5;
    const int n0 = blockIdx.x << 7, m0 = blockIdx.y << 7;
    const int K2 = K * 2;

    const char* gA0 = (const char*)(Ah + (size_t)m0 * K);
    const char* gA1 = (const char*)(Al + (size_t)m0 * K);
    const char* gB0 = (const char*)(Bh + (size_t)n0 * K);
    const char* gB1 = (const char*)(Bl + (size_t)n0 * K);

    cp_tile(smb +     0, gA0, K2, 0, tid);
    cp_tile(smb + 16384, gA1, K2, 0, tid);
    cp_tile(smb + 32768, gB0, K2, 0, tid);
    cp_tile(smb + 49152, gB1, K2, 0, tid);
    CP_COMMIT();

    float acc[4][4][4];
#pragma unroll
    for (int i = 0; i < 4; i++)
#pragma unroll
        for (int j = 0; j < 4; j++)
#pragma unroll
            for (int q = 0; q < 4; q++) acc[i][j][q] = 0.f;

    const int arow = (lane & 7) + ((lane >> 3) & 1) * 8;
    const int abit = (lane >> 4) & 1;
    const int brow = (lane & 7) + ((lane >> 4) & 1) * 8;
    const int bbit = (lane >> 3) & 1;

    const int NIT = K >> 6;
    for (int it = 0; it < NIT; it++) {
        const uint32_t cur = smb + (uint32_t)(it & 1) * 65536u;
        if (it + 1 < NIT) {
            const uint32_t nxt = smb + (uint32_t)((it + 1) & 1) * 65536u;
            const int kb = (it + 1) << 7;
            cp_tile(nxt +     0, gA0, K2, kb, tid);
            cp_tile(nxt + 16384, gA1, K2, kb, tid);
            cp_tile(nxt + 32768, gB0, K2, kb, tid);
            cp_tile(nxt + 49152, gB1, K2, kb, tid);
            CP_COMMIT();
            CP_WAIT1();
        } else {
            CP_WAIT0();
        }
        __syncthreads();

#pragma unroll
        for (int ks = 0; ks < 4; ks++) {
            uint32_t a_h[4][4], a_l[4][4], b_h[2][4], b_l[2][4];
#pragma unroll
            for (int i = 0; i < 4; i++) {
                int r = wm + (i << 4) + arow;
                uint32_t off = (uint32_t)r * 128 +
                               ((((ks << 1) + abit) ^ (r & 7)) << 4);
                ldsm4(a_h[i], cur + off);
                ldsm4(a_l[i], cur + 16384 + off);
            }
#pragma unroll
            for (int j = 0; j < 2; j++) {
                int r = wn + (j << 4) + brow;
                uint32_t off = (uint32_t)r * 128 +
                               ((((ks << 1) + bbit) ^ (r & 7)) << 4);
                ldsm4(b_h[j], cur + 32768 + off);
                ldsm4(b_l[j], cur + 49152 + off);
            }
#pragma unroll
            for (int i = 0; i < 4; i++)
#pragma unroll
                for (int jj = 0; jj < 4; jj++) {
                    const uint32_t* bh = &b_h[jj >> 1][(jj & 1) << 1];
                    const uint32_t* bl = &b_l[jj >> 1][(jj & 1) << 1];
                    mma16816(acc[i][jj], a_h[i], bh);
                    mma16816(acc[i][jj], a_h[i], bl);
                    mma16816(acc[i][jj], a_l[i], bh);
                }
        }
        __syncthreads();
    }

#pragma unroll
    for (int i = 0; i < 4; i++) {
        int row = m0 + wm + (i << 4) + (lane >> 2);
#pragma unroll
        for (int jj = 0; jj < 4; jj++) {
            int col = n0 + wn + (jj << 3) + ((lane & 3) << 1);
            float* p0 = C + (size_t)row * N + col;
            float* p1 = C + (size_t)(row + 8) * N + col;
            p0[0] = acc[i][jj][0]; p0[1] = acc[i][jj][1];
            p1[0] = acc[i][jj][2]; p1[1] = acc[i][jj][3];
        }
    }
}

// ---------------------------------------------------------------------------
// HMMA flash attention, bf16x3 split, sliding window + GQA.
// Grid (B*NH, S/128), 256 thr / 8 warps, warp = 16 q rows.
// smem: Qh 32K | Ql 32K | 2 stages x (Kh 16K | Kl 16K | Vh 16K | Vl 16K) | mk
// All tiles: 256B rows (16 chunks of 16B), chunk swizzle c ^ (r & 7).
// ---------------------------------------------------------------------------
#define ATT_SMEM (196608 + 512)

__device__ __forceinline__ void att_ld_kv(uint32_t dst, const char* g, int tid)
{
    // 16KB tile: 64 rows x 256B, gmem row stride 2048B
#pragma unroll
    for (int t = 0; t < 4; t++) {
        int idx = tid + (t << 8);
        int r = idx >> 4, c = idx & 15;
        uint32_t phys = dst + r * 256 + ((c ^ (r & 7)) << 4);
        cp16(phys, g + (size_t)r * 2048 + (c << 4));
    }
}

__global__ __launch_bounds__(256, 1)
void attn_mma(const __nv_bfloat16* __restrict__ Qh_, const __nv_bfloat16* __restrict__ Ql_,
              const __nv_bfloat16* __restrict__ Kh_, const __nv_bfloat16* __restrict__ Kl_,
              const __nv_bfloat16* __restrict__ Vh_, const __nv_bfloat16* __restrict__ Vl_,
              const int* __restrict__ am,
              __nv_bfloat16* __restrict__ Oh_, __nv_bfloat16* __restrict__ Ol_)
{
    extern __shared__ __align__(128) char smc[];
    const uint32_t smb = smem_u32(smc);
    int* mk = (int*)(smc + 196608);   // [2][64]

    const int tid = threadIdx.x;
    const int lane = tid & 31, wid = tid >> 5;
    const int b = blockIdx.x >> 5, h = blockIdx.x & 31;
    const int kvh = h >> 2;
    const int qi0 = blockIdx.y << 7;
    const int wm = wid << 4;

    // ---- load Q tile (128 rows x 128 hd, hi+lo) via cp.async ----
    {
        const char* gqh = (const char*)(Qh_ + ((size_t)(b * Sq + qi0) * NHq + h) * HDq);
        const char* gql = (const char*)(Ql_ + ((size_t)(b * Sq + qi0) * NHq + h) * HDq);
#pragma unroll
        for (int t = 0; t < 8; t++) {
            int idx = tid + (t << 8);
            int r = idx >> 4, c = idx & 15;
            uint32_t sw = r * 256 + ((c ^ (r & 7)) << 4);
            const size_t go = (size_t)r * 8192 + (c << 4);
            cp16(smb + sw, gqh + go);
            cp16(smb + 32768 + sw, gql + go);
        }
    }

    const int klo = (qi0 >= WINq) ? qi0 - WINq : 0;
    const int NT = ((qi0 + 64) - klo) / 64 + 1;

    const char* gkh = (const char*)(Kh_ + ((size_t)b * Sq * NKVq + kvh) * HDq);
    const char* gkl = (const char*)(Kl_ + ((size_t)b * Sq * NKVq + kvh) * HDq);
    const char* gvh = (const char*)(Vh_ + ((size_t)b * Sq * NKVq + kvh) * HDq);
    const char* gvl = (const char*)(Vl_ + ((size_t)b * Sq * NKVq + kvh) * HDq);

    // prologue: KV tile 0 into stage 0 (same cp group as Q)
    {
        uint32_t stg = smb + 65536;
        att_ld_kv(stg,         gkh + (size_t)klo * 2048, tid);
        att_ld_kv(stg + 16384, gkl + (size_t)klo * 2048, tid);
        att_ld_kv(stg + 32768, gvh + (size_t)klo * 2048, tid);
        att_ld_kv(stg + 49152, gvl + (size_t)klo * 2048, tid);
        if (tid < 64) mk[tid] = am[b * Sq + klo + tid];
    }
    CP_COMMIT();

    float m0r = -1e30f, m1r = -1e30f, l0 = 0.f, l1 = 0.f;
    float acc[16][4];
#pragma unroll
    for (int i = 0; i < 16; i++)
#pragma unroll
        for (int q = 0; q < 4; q++) acc[i][q] = 0.f;

    const int arow = (lane & 7) + ((lane >> 3) & 1) * 8;
    const int abit = (lane >> 4) & 1;
    const int brow = (lane & 7) + ((lane >> 4) & 1) * 8;
    const int bbit = (lane >> 3) & 1;
    const int vrow = (lane & 7) + ((lane >> 3) & 1) * 8;
    const int vcb  = (lane >> 4) & 1;

    const int row0 = qi0 + wm + (lane >> 2);
    const int row1 = row0 + 8;
    const float scale = 0.08838834764831845f;

    for (int t = 0; t < NT; t++) {
        const int k0 = klo + t * 64;
        if (t + 1 < NT) {
            uint32_t stg = smb + 65536 + (uint32_t)((t + 1) & 1) * 65536u;
            const size_t go = (size_t)(k0 + 64) * 2048;
            att_ld_kv(stg,         gkh + go, tid);
            att_ld_kv(stg + 16384, gkl + go, tid);
            att_ld_kv(stg + 32768, gvh + go, tid);
            att_ld_kv(stg + 49152, gvl + go, tid);
            if (tid < 64) mk[((t + 1) & 1) * 64 + tid] = am[b * Sq + k0 + 64 + tid];
            CP_COMMIT();
            CP_WAIT1();
        } else {
            CP_WAIT0();
        }
        __syncthreads();

        const uint32_t stg = smb + 65536 + (uint32_t)(t & 1) * 65536u;

        // ---- S = Q @ K^T (bf16x3) ----
        float s[8][4];
#pragma unroll
        for (int nf = 0; nf < 8; nf++)
#pragma unroll
            for (int q = 0; q < 4; q++) s[nf][q] = 0.f;

#pragma unroll
        for (int ks = 0; ks < 8; ks++) {
            uint32_t aqh[4], aql[4];
            {
                int r = wm + arow;
                uint32_t off = (uint32_t)r * 256 +
                               ((((ks << 1) + abit) ^ (r & 7)) << 4);
                ldsm4(aqh, smb + off);
                ldsm4(aql, smb + 32768 + off);
            }
            uint32_t kh4[4][4], kl4[4][4];
#pragma unroll
            for (int j = 0; j < 4; j++) {
                int r = (j << 4) + brow;
                uint32_t off = (uint32_t)r * 256 +
                               ((((ks << 1) + bbit) ^ (r & 7)) << 4);
                ldsm4(kh4[j], stg + off);
                ldsm4(kl4[j], stg + 16384 + off);
            }
#pragma unroll
            for (int nf = 0; nf < 8; nf++) {
                const uint32_t* bh = &kh4[nf >> 1][(nf & 1) << 1];
                const uint32_t* bl = &kl4[nf >> 1][(nf & 1) << 1];
                mma16816(s[nf], aqh, bh);
                mma16816(s[nf], aqh, bl);
                mma16816(s[nf], aql, bh);
            }
        }

        // ---- mask + online softmax (fp32, FMA-pipe exp) ----
        float mx0 = -1e30f, mx1 = -1e30f;
#pragma unroll
        for (int nf = 0; nf < 8; nf++) {
#pragma unroll
            for (int q = 0; q < 4; q++) {
                int col = k0 + (nf << 3) + ((lane & 3) << 1) + (q & 1);
                int row = (q < 2) ? row0 : row1;
                bool valid = (col <= row) && (col >= row - WINq) &&
                             (mk[(t & 1) * 64 + col - k0] > 0);
                float sv = valid ? s[nf][q] * scale : -1e30f;
                s[nf][q] = sv;
                if (q < 2) mx0 = fmaxf(mx0, sv); else mx1 = fmaxf(mx1, sv);
            }
        }
        mx0 = fmaxf(mx0, __shfl_xor_sync(0xffffffffu, mx0, 1));
        mx0 = fmaxf(mx0, __shfl_xor_sync(0xffffffffu, mx0, 2));
        mx1 = fmaxf(mx1, __shfl_xor_sync(0xffffffffu, mx1, 1));
        mx1 = fmaxf(mx1, __shfl_xor_sync(0xffffffffu, mx1, 2));

        float newm0 = fmaxf(m0r, mx0), newm1 = fmaxf(m1r, mx1);
        float alpha0 = fexp(m0r - newm0), alpha1 = fexp(m1r - newm1);
        float rs0 = 0.f, rs1 = 0.f;
#pragma unroll
        for (int nf = 0; nf < 8; nf++) {
#pragma unroll
            for (int q = 0; q < 4; q++) {
                float p = fexp(s[nf][q] - ((q < 2) ? newm0 : newm1));
                s[nf][q] = p;
                if (q < 2) rs0 += p; else rs1 += p;
            }
        }
        rs0 += __shfl_xor_sync(0xffffffffu, rs0, 1);
        rs0 += __shfl_xor_sync(0xffffffffu, rs0, 2);
        rs1 += __shfl_xor_sync(0xffffffffu, rs1, 1);
        rs1 += __shfl_xor_sync(0xffffffffu, rs1, 2);

        l0 = l0 * alpha0 + rs0;  m0r = newm0;
        l1 = l1 * alpha1 + rs1;  m1r = newm1;

#pragma unroll
        for (int i = 0; i < 16; i++) {
            acc[i][0] *= alpha0; acc[i][1] *= alpha0;
            acc[i][2] *= alpha1; acc[i][3] *= alpha1;
        }

        // ---- build P fragments (hi/lo split, in-register) ----
        uint32_t ph[8][2], pl[8][2];
#pragma unroll
        for (int nf = 0; nf < 8; nf++) {
            float p0 = s[nf][0], p1 = s[nf][1], p2 = s[nf][2], p3 = s[nf][3];
            __nv_bfloat16 h0 = __float2bfloat16(p0), h1 = __float2bfloat16(p1);
            __nv_bfloat16 h2 = __float2bfloat16(p2), h3 = __float2bfloat16(p3);
            ph[nf][0] = (uint32_t)__bfloat16_as_ushort(h0) |
                        ((uint32_t)__bfloat16_as_ushort(h1) << 16);
            ph[nf][1] = (uint32_t)__bfloat16_as_ushort(h2) |
                        ((uint32_t)__bfloat16_as_ushort(h3) << 16);
            pl[nf][0] = pack_bf2(p0 - __bfloat162float(h0), p1 - __bfloat162float(h1));
            pl[nf][1] = pack_bf2(p2 - __bfloat162float(h2), p3 - __bfloat162float(h3));
        }

        // ---- acc += P @ V (bf16x3) ----
#pragma unroll
        for (int ks = 0; ks < 4; ks++) {
            uint32_t pa_h[4] = { ph[2*ks][0], ph[2*ks][1], ph[2*ks+1][0], ph[2*ks+1][1] };
            uint32_t pa_l[4] = { pl[2*ks][0], pl[2*ks][1], pl[2*ks+1][0], pl[2*ks+1][1] };
#pragma unroll
            for (int h16 = 0; h16 < 8; h16++) {
                int r = (ks << 4) + vrow;
                int c = (h16 << 1) + vcb;
                uint32_t off = (uint32_t)r * 256 + ((c ^ (r & 7)) << 4);
                uint32_t vh4[4], vl4[4];
                ldsm4t(vh4, stg + 32768 + off);
                ldsm4t(vl4, stg + 49152 + off);
                mma16816(acc[2*h16],     pa_h, &vh4[0]);
                mma16816(acc[2*h16],     pa_l, &vh4[0]);
                mma16816(acc[2*h16],     pa_h, &vl4[0]);
                mma16816(acc[2*h16 + 1], pa_h, &vh4[2]);
                mma16816(acc[2*h16 + 1], pa_l, &vh4[2]);
                mma16816(acc[2*h16 + 1], pa_h, &vl4[2]);
            }
        }
        __syncthreads();
    }

    // ---- epilogue: write bf16 hi/lo attention output [Mtot][4096] ----
    const float inv0 = 1.0f / l0, inv1 = 1.0f / l1;
    const size_t r0g = (size_t)(b * Sq + row0) * 4096 + h * 128;
    const size_t r1g = (size_t)(b * Sq + row1) * 4096 + h * 128;
#pragma unroll
    for (int nf = 0; nf < 16; nf++) {
        int col = (nf << 3) + ((lane & 3) << 1);
        float o0 = acc[nf][0] * inv0, o1 = acc[nf][1] * inv0;
        float o2 = acc[nf][2] * inv1, o3 = acc[nf][3] * inv1;
        __nv_bfloat16 h0 = __float2bfloat16(o0), h1 = __float2bfloat16(o1);
        __nv_bfloat16 h2 = __float2bfloat16(o2), h3 = __float2bfloat16(o3);
        *(uint32_t*)(Oh_ + r0g + col) = (uint32_t)__bfloat16_as_ushort(h0) |
                                        ((uint32_t)__bfloat16_as_ushort(h1) << 16);
        *(uint32_t*)(Oh_ + r1g + col) = (uint32_t)__bfloat16_as_ushort(h2) |
                                        ((uint32_t)__bfloat16_as_ushort(h3) << 16);
        *(uint32_t*)(Ol_ + r0g + col) = pack_bf2(o0 - __bfloat162float(h0),
                                                 o1 - __bfloat162float(h1));
        *(uint32_t*)(Ol_ + r1g + col) = pack_bf2(o2 - __bfloat162float(h2),
                                                 o3 - __bfloat162float(h3));
    }
}

// ---------------------------------------------------------------------------
// Launch
// ---------------------------------------------------------------------------
extern "C" void kernel_launch(void* const* d_in, const int* in_sizes, int n_in,
                              void* d_out, int out_size)
{
    const float* hs    = (const float*)d_in[0];
    const int*   amask = (const int*)  d_in[1];
    const int*   pos   = (const int*)  d_in[2];
    const float* qw    = (const float*)d_in[3];
    const float* kw    = (const float*)d_in[4];
    const float* vw    = (const float*)d_in[5];
    const float* ow    = (const float*)d_in[6];
    float*       out   = (float*)d_out;

    float *gq, *gk, *gv;
    cudaGetSymbolAddress((void**)&gq, g_q);
    cudaGetSymbolAddress((void**)&gk, g_k);
    cudaGetSymbolAddress((void**)&gv, g_v);

    __nv_bfloat16 *ah, *al, *wqh, *wql, *wkh, *wkl, *wvh, *wvl, *woh, *wol, *ath, *atl;
    __nv_bfloat16 *qh, *ql, *kh, *kl, *vh, *vl;
    cudaGetSymbolAddress((void**)&ah,  sA_hi);  cudaGetSymbolAddress((void**)&al,  sA_lo);
    cudaGetSymbolAddress((void**)&wqh, sWq_hi); cudaGetSymbolAddress((void**)&wql, sWq_lo);
    cudaGetSymbolAddress((void**)&wkh, sWk_hi); cudaGetSymbolAddress((void**)&wkl, sWk_lo);
    cudaGetSymbolAddress((void**)&wvh, sWv_hi); cudaGetSymbolAddress((void**)&wvl, sWv_lo);
    cudaGetSymbolAddress((void**)&woh, sWo_hi); cudaGetSymbolAddress((void**)&wol, sWo_lo);
    cudaGetSymbolAddress((void**)&ath, sAt_hi); cudaGetSymbolAddress((void**)&atl, sAt_lo);
    cudaGetSymbolAddress((void**)&qh,  sQh);    cudaGetSymbolAddress((void**)&ql,  sQl);
    cudaGetSymbolAddress((void**)&kh,  sKh);    cudaGetSymbolAddress((void**)&kl,  sKl);
    cudaGetSymbolAddress((void**)&vh,  sVh);    cudaGetSymbolAddress((void**)&vl,  sVl);

    const int gemm_smem = 131072;
    cudaFuncSetAttribute(gemm_mma_bf16x3, cudaFuncAttributeMaxDynamicSharedMemorySize,
                         gemm_smem);
    cudaFuncSetAttribute(attn_mma, cudaFuncAttributeMaxDynamicSharedMemorySize,
                         ATT_SMEM);

    // 1. split hidden_states -> bf16 hi/lo
    {
        int n4 = (Mtot * HIDq) / 4;
        split_kernel<<<(n4 + 255) / 256, 256>>>((const float4*)hs, (uint2*)ah, (uint2*)al, n4);
    }
    // 2. transpose + split weights to [N, K] bf16 hi/lo
    transpose_split<<<dim3(128, 128), dim3(32, 8)>>>(qw, wqh, wql, HIDq, 4096);
    transpose_split<<<dim3(32, 128),  dim3(32, 8)>>>(kw, wkh, wkl, HIDq, 1024);
    transpose_split<<<dim3(32, 128),  dim3(32, 8)>>>(vw, wvh, wvl, HIDq, 1024);
    transpose_split<<<dim3(128, 128), dim3(32, 8)>>>(ow, woh, wol, 4096, HIDq);

    // 3. QKV projections (HMMA)
    gemm_mma_bf16x3<<<dim3(32, 32), 256, gemm_smem>>>(ah, al, wqh, wql, gq, 4096, HIDq);
    gemm_mma_bf16x3<<<dim3(8, 32),  256, gemm_smem>>>(ah, al, wkh, wkl, gk, 1024, HIDq);
    gemm_mma_bf16x3<<<dim3(8, 32),  256, gemm_smem>>>(ah, al, wvh, wvl, gv, 1024, HIDq);

    // 4. RoPE + split to bf16 hi/lo; V split
    {
        int tq = Mtot * NHq * 64;
        int tk = Mtot * NKVq * 64;
        rope_split<<<(tq + 255) / 256, 256>>>(gq, pos, qh, ql, NHq, tq);
        rope_split<<<(tk + 255) / 256, 256>>>(gk, pos, kh, kl, NKVq, tk);
        int n4 = (Mtot * NKVq * HDq) / 4;
        split_kernel<<<(n4 + 255) / 256, 256>>>((const float4*)gv, (uint2*)vh, (uint2*)vl, n4);
    }

    // 5. HMMA attention -> bf16 hi/lo output (pre-split for O GEMM)
    attn_mma<<<dim3(Bq * NHq, Sq / 128), 256, ATT_SMEM>>>(qh, ql, kh, kl, vh, vl,
                                                          amask, ath, atl);

    // 6. O projection into d_out
    gemm_mma_bf16x3<<<dim3(32, 32), 256, gemm_smem>>>(ath, atl, woh, wol, out, HIDq, 4096);
}